// round 2
// baseline (speedup 1.0000x reference)
#include <cuda_runtime.h>

typedef unsigned long long u64;

#define NB      16
#define SS      4096
#define D4      128          // float4 (16B) per row
#define HALO    19
#define CHUNK   64
#define RING    83           // CHUNK + HALO rows resident
#define TM      8            // rows per warp register tile
#define NWARPS  8
#define NTHR    256
#define NSEG    9
#define SEGROWS 456          // last segment gets 448
#define NBLK    (NB * NSEG)  // 144
#define CNT_DIST 40815       // sum_{k=10}^{19} (4096 - k)

__device__ float2 g_part[NBLK];

__device__ __forceinline__ u64 ffma2(u64 a, u64 b, u64 c) {
    u64 d;
    asm("fma.rn.f32x2 %0, %1, %2, %3;" : "=l"(d) : "l"(a), "l"(b), "l"(c));
    return d;
}
__device__ __forceinline__ u64 fmul2(u64 a, u64 b) {
    u64 d;
    asm("mul.rn.f32x2 %0, %1, %2;" : "=l"(d) : "l"(a), "l"(b));
    return d;
}
__device__ __forceinline__ u64 fadd2(u64 a, u64 b) {
    u64 d;
    asm("add.rn.f32x2 %0, %1, %2;" : "=l"(d) : "l"(a), "l"(b));
    return d;
}
__device__ __forceinline__ u64 pack2(float x, float y) {
    u64 d;
    asm("mov.b64 %0, {%1, %2};" : "=l"(d) : "f"(x), "f"(y));
    return d;
}
__device__ __forceinline__ float hsum2(u64 v) {
    float x, y;
    asm("mov.b64 {%0,%1}, %2;" : "=f"(x), "=f"(y) : "l"(v));
    return x + y;
}
__device__ __forceinline__ float wred(float v) {
    v += __shfl_xor_sync(0xffffffffu, v, 16);
    v += __shfl_xor_sync(0xffffffffu, v, 8);
    v += __shfl_xor_sync(0xffffffffu, v, 4);
    v += __shfl_xor_sync(0xffffffffu, v, 2);
    v += __shfl_xor_sync(0xffffffffu, v, 1);
    return v;
}

extern __shared__ ulonglong2 smem[];   // RING * D4 entries of 16B (unit rows)

__global__ void __launch_bounds__(NTHR, 1)
tcl_main(const float* __restrict__ hs) {
    const int seg  = blockIdx.x;
    const int b    = blockIdx.y;
    const int t0   = seg * SEGROWS;
    const int tEnd = (t0 + SEGROWS < SS) ? (t0 + SEGROWS) : SS;
    const int nch  = (tEnd - t0 + CHUNK - 1) / CHUNK;

    const int tid  = threadIdx.x;
    const int wid  = tid >> 5;
    const int lane = tid & 31;

    const ulonglong2* __restrict__ hb =
        reinterpret_cast<const ulonglong2*>(hs) + (size_t)b * SS * D4;

    u64   accAa = 0ull, accAb = 0ull;  // packed adjacent-sum accumulators
    float accD  = 0.f;                 // distant relu sum (lane-replicated)

    for (int ci = 0; ci < nch; ++ci) {
        const int c0     = t0 + ci * CHUNK;
        const int loadLo = ci ? (c0 + HALO) : c0;
        const int loadHi = (c0 + RING < SS) ? (c0 + RING) : SS;

        // ── load + normalize: one warp per row ──────────────────────────
        for (int r = loadLo + wid; r < loadHi; r += NWARPS) {
            const ulonglong2* __restrict__ src = hb + (size_t)r * D4;
            ulonglong2 v0 = src[lane];
            ulonglong2 v1 = src[lane + 32];
            ulonglong2 v2 = src[lane + 64];
            ulonglong2 v3 = src[lane + 96];
            u64 p = 0ull, q = 0ull;
            p = ffma2(v0.x, v0.x, p); q = ffma2(v0.y, v0.y, q);
            p = ffma2(v1.x, v1.x, p); q = ffma2(v1.y, v1.y, q);
            p = ffma2(v2.x, v2.x, p); q = ffma2(v2.y, v2.y, q);
            p = ffma2(v3.x, v3.x, p); q = ffma2(v3.y, v3.y, q);
            float ss   = wred(hsum2(fadd2(p, q)));
            float invn = rsqrtf(ss);
            u64   s2   = pack2(invn, invn);
            v0.x = fmul2(v0.x, s2); v0.y = fmul2(v0.y, s2);
            v1.x = fmul2(v1.x, s2); v1.y = fmul2(v1.y, s2);
            v2.x = fmul2(v2.x, s2); v2.y = fmul2(v2.y, s2);
            v3.x = fmul2(v3.x, s2); v3.y = fmul2(v3.y, s2);
            int slot = (r - t0) % RING;
            ulonglong2* dst = smem + slot * D4;
            dst[lane]      = v0;
            dst[lane + 32] = v1;
            dst[lane + 64] = v2;
            dst[lane + 96] = v3;
        }
        __syncthreads();

        // ── compute ─────────────────────────────────────────────────────
        const int rowEnd = (c0 + CHUNK < tEnd) ? (c0 + CHUNK) : tEnd;
        const int tt     = c0 + wid * TM;
        if (tt < rowEnd) {            // whole 8-row tile valid (rows are 8-aligned)
            const int sb = (tt - t0) % RING;

            ulonglong2 a[TM][4];
#pragma unroll
            for (int i = 0; i < TM; ++i) {
                int sl = sb + i; if (sl >= RING) sl -= RING;
                const ulonglong2* row = smem + sl * D4;
#pragma unroll
                for (int j = 0; j < 4; ++j) a[i][j] = row[lane + 32 * j];
            }

#pragma unroll
            for (int d = 1; d <= TM + HALO - 1; ++d) {
                int r = tt + d;
                if (r < SS) {         // warp-uniform
                    int sl = sb + d; if (sl >= RING) sl -= RING;
                    const ulonglong2* row = smem + sl * D4;
                    ulonglong2 s0 = row[lane];
                    ulonglong2 s1 = row[lane + 32];
                    ulonglong2 s2 = row[lane + 64];
                    ulonglong2 s3 = row[lane + 96];

                    if (d <= TM) {    // adjacent pair (i = d-1, k = 1): linear, no reduction
                        const int i = d - 1;
                        accAa = ffma2(a[i][0].x, s0.x, accAa);
                        accAb = ffma2(a[i][0].y, s0.y, accAb);
                        accAa = ffma2(a[i][1].x, s1.x, accAa);
                        accAb = ffma2(a[i][1].y, s1.y, accAb);
                        accAa = ffma2(a[i][2].x, s2.x, accAa);
                        accAb = ffma2(a[i][2].y, s2.y, accAb);
                        accAa = ffma2(a[i][3].x, s3.x, accAa);
                        accAb = ffma2(a[i][3].y, s3.y, accAb);
                    }

#pragma unroll
                    for (int k = 10; k <= 19; ++k) {
                        const int i = d - k;
                        if (0 <= i && i < TM) {   // compile-time pruned
                            u64 q1 = 0ull, q2 = 0ull;
                            q1 = ffma2(a[i][0].x, s0.x, q1);
                            q2 = ffma2(a[i][0].y, s0.y, q2);
                            q1 = ffma2(a[i][1].x, s1.x, q1);
                            q2 = ffma2(a[i][1].y, s1.y, q2);
                            q1 = ffma2(a[i][2].x, s2.x, q1);
                            q2 = ffma2(a[i][2].y, s2.y, q2);
                            q1 = ffma2(a[i][3].x, s3.x, q1);
                            q2 = ffma2(a[i][3].y, s3.y, q2);
                            float sim = wred(hsum2(fadd2(q1, q2)));
                            accD += fmaxf(0.5f - sim, 0.f);
                        }
                    }
                }
            }
        }
        __syncthreads();
    }

    // accA is per-lane partial; accD is lane-replicated (post-wred values)
    float aLane = hsum2(accAa) + hsum2(accAb);
    float aWarp = wred(aLane);

    __shared__ float rA[NWARPS], rD[NWARPS];
    if (lane == 0) { rA[wid] = aWarp; rD[wid] = accD; }
    __syncthreads();
    if (tid == 0) {
        float sA = 0.f, sD = 0.f;
#pragma unroll
        for (int w = 0; w < NWARPS; ++w) { sA += rA[w]; sD += rD[w]; }
        g_part[b * NSEG + seg] = make_float2(sA, sD);
    }
}

__global__ void tcl_final(float* __restrict__ out) {
    int tid = threadIdx.x;   // 32 threads
    float a = 0.f, dd = 0.f;
    for (int i = tid; i < NBLK; i += 32) {
        float2 p = g_part[i];
        a += p.x; dd += p.y;
    }
    a  = wred(a);
    dd = wred(dd);
    if (tid == 0) {
        float adj  = 1.f - a / ((float)NB * (float)(SS - 1));
        float dist = dd / ((float)NB * (float)CNT_DIST);
        out[0] = adj + dist;
    }
}

extern "C" void kernel_launch(void* const* d_in, const int* in_sizes, int n_in,
                              void* d_out, int out_size) {
    (void)in_sizes; (void)n_in; (void)out_size;
    const float* hs = (const float*)d_in[0];

    const size_t shmem = (size_t)RING * D4 * sizeof(ulonglong2);  // 169,984 B
    cudaFuncSetAttribute(tcl_main, cudaFuncAttributeMaxDynamicSharedMemorySize,
                         (int)shmem);

    dim3 grid(NSEG, NB);
    tcl_main<<<grid, NTHR, shmem>>>(hs);
    tcl_final<<<1, 32>>>((float*)d_out);
}

// round 4
// speedup vs baseline: 1.3535x; 1.3535x over previous
#include <cuda_runtime.h>

typedef unsigned long long u64;

#define NB      16
#define SS      4096
#define D4      128          // float4 per row
#define RPAD    129          // padded float4 stride in smem
#define HALO    19
#define CHUNK   64
#define RING    83
#define TM      8
#define NWARPS  8
#define NTHR    256
#define NSEG    9
#define SEGROWS 456          // 8 segs of 456 + last 448 = 4096
#define NBLK    (NB * NSEG)  // 144
#define CNT_DIST 40815       // sum_{k=10}^{19} (4096 - k)

__device__ float2       g_part[NBLK];
__device__ unsigned int g_count = 0;

__device__ __forceinline__ u64 ffma2(u64 a, u64 b, u64 c) {
    u64 d;
    asm("fma.rn.f32x2 %0, %1, %2, %3;" : "=l"(d) : "l"(a), "l"(b), "l"(c));
    return d;
}
__device__ __forceinline__ u64 fmul2(u64 a, u64 b) {
    u64 d;
    asm("mul.rn.f32x2 %0, %1, %2;" : "=l"(d) : "l"(a), "l"(b));
    return d;
}
__device__ __forceinline__ u64 fadd2(u64 a, u64 b) {
    u64 d;
    asm("add.rn.f32x2 %0, %1, %2;" : "=l"(d) : "l"(a), "l"(b));
    return d;
}
__device__ __forceinline__ u64 pack2(float x, float y) {
    u64 d;
    asm("mov.b64 %0, {%1, %2};" : "=l"(d) : "f"(x), "f"(y));
    return d;
}
__device__ __forceinline__ float hsum2(u64 v) {
    float x, y;
    asm("mov.b64 {%0,%1}, %2;" : "=f"(x), "=f"(y) : "l"(v));
    return x + y;
}
__device__ __forceinline__ float wred(float v) {
    v += __shfl_xor_sync(0xffffffffu, v, 16);
    v += __shfl_xor_sync(0xffffffffu, v, 8);
    v += __shfl_xor_sync(0xffffffffu, v, 4);
    v += __shfl_xor_sync(0xffffffffu, v, 2);
    v += __shfl_xor_sync(0xffffffffu, v, 1);
    return v;
}

extern __shared__ ulonglong2 smem[];   // RING rows * RPAD float4 (unit rows)

__global__ void __launch_bounds__(NTHR, 1)
tcl_main(const float* __restrict__ hs, float* __restrict__ out) {
    const int seg  = blockIdx.x;
    const int b    = blockIdx.y;
    const int t0   = seg * SEGROWS;
    const int tEnd = (t0 + SEGROWS < SS) ? (t0 + SEGROWS) : SS;
    const int nch  = (tEnd - t0 + CHUNK - 1) / CHUNK;

    const int tid  = threadIdx.x;
    const int wid  = tid >> 5;
    const int lane = tid & 31;

    const ulonglong2* __restrict__ hb =
        reinterpret_cast<const ulonglong2*>(hs) + (size_t)b * SS * D4;

    u64   accAa = 0ull, accAb = 0ull;  // adjacent sum, packed, reduction-free
    float accD  = 0.f;                 // distant relu sum (lane-replicated)

    for (int ci = 0; ci < nch; ++ci) {
        const int c0     = t0 + ci * CHUNK;
        const int loadLo = ci ? (c0 + HALO) : c0;
        const int loadHi = (c0 + RING < SS) ? (c0 + RING) : SS;

        // ── Phase A: load + normalize. 8 threads per row, 32 rows/pass.
        // MLP-16 loads; squares folded into load stream; 3-shfl group
        // reduction; store with per-slice rotation (i+q)&15 so the 8 slices
        // of a row never collide on banks. The rotation is identical for
        // every row, so all dot products / norms are unaffected.
        for (int r0 = loadLo; r0 < loadHi; r0 += 32) {
            int row  = r0 + (tid >> 3);
            int ok   = row < loadHi;
            int rowc = ok ? row : (loadHi - 1);
            int q    = tid & 7;
            const ulonglong2* __restrict__ src = hb + (size_t)rowc * D4 + q * 16;

            ulonglong2 v[16];
#pragma unroll
            for (int i = 0; i < 16; ++i) v[i] = src[i];

            u64 p0 = 0ull, p1 = 0ull, p2 = 0ull, p3 = 0ull;
#pragma unroll
            for (int i = 0; i < 16; i += 2) {
                p0 = ffma2(v[i].x,   v[i].x,   p0);
                p1 = ffma2(v[i].y,   v[i].y,   p1);
                p2 = ffma2(v[i+1].x, v[i+1].x, p2);
                p3 = ffma2(v[i+1].y, v[i+1].y, p3);
            }
            float s = hsum2(fadd2(fadd2(p0, p1), fadd2(p2, p3)));
            s += __shfl_xor_sync(0xffffffffu, s, 1);
            s += __shfl_xor_sync(0xffffffffu, s, 2);
            s += __shfl_xor_sync(0xffffffffu, s, 4);
            float invn = rsqrtf(s);
            u64 iv = pack2(invn, invn);

            if (ok) {
                int slot = (row - t0) % RING;
                ulonglong2* dst = smem + (size_t)slot * RPAD + q * 16;
#pragma unroll
                for (int i = 0; i < 16; ++i) {
                    ulonglong2 w;
                    w.x = fmul2(v[i].x, iv);
                    w.y = fmul2(v[i].y, iv);
                    dst[(i + q) & 15] = w;
                }
            }
        }
        __syncthreads();

        // ── Phase B: banded dot products on unit rows ────────────────────
        const int rowEnd = (c0 + CHUNK < tEnd) ? (c0 + CHUNK) : tEnd;
        const int tt     = c0 + wid * TM;
        if (tt < rowEnd) {                    // whole 8-row tile valid
            const int sb = (tt - t0) % RING;

            ulonglong2 a[TM][4];
#pragma unroll
            for (int i = 0; i < TM; ++i) {
                int sl = sb + i; if (sl >= RING) sl -= RING;
                const ulonglong2* row = smem + (size_t)sl * RPAD;
#pragma unroll
                for (int j = 0; j < 4; ++j) a[i][j] = row[lane + 32 * j];
            }

#pragma unroll
            for (int d = 1; d <= TM + HALO - 1; ++d) {
                int r = tt + d;
                if (r < SS) {                 // warp-uniform
                    int sl = sb + d; if (sl >= RING) sl -= RING;
                    const ulonglong2* row = smem + (size_t)sl * RPAD;
                    ulonglong2 s0 = row[lane];
                    ulonglong2 s1 = row[lane + 32];
                    ulonglong2 s2 = row[lane + 64];
                    ulonglong2 s3 = row[lane + 96];

                    if (d <= TM) {            // adjacent pair: no reduction
                        const int i = d - 1;
                        accAa = ffma2(a[i][0].x, s0.x, accAa);
                        accAb = ffma2(a[i][0].y, s0.y, accAb);
                        accAa = ffma2(a[i][1].x, s1.x, accAa);
                        accAb = ffma2(a[i][1].y, s1.y, accAb);
                        accAa = ffma2(a[i][2].x, s2.x, accAa);
                        accAb = ffma2(a[i][2].y, s2.y, accAb);
                        accAa = ffma2(a[i][3].x, s3.x, accAa);
                        accAb = ffma2(a[i][3].y, s3.y, accAb);
                    }

#pragma unroll
                    for (int k = 10; k <= 19; ++k) {
                        const int i = d - k;
                        if (0 <= i && i < TM) {   // compile-time pruned
                            u64 q1 = 0ull, q2 = 0ull;
                            q1 = ffma2(a[i][0].x, s0.x, q1);
                            q2 = ffma2(a[i][0].y, s0.y, q2);
                            q1 = ffma2(a[i][1].x, s1.x, q1);
                            q2 = ffma2(a[i][1].y, s1.y, q2);
                            q1 = ffma2(a[i][2].x, s2.x, q1);
                            q2 = ffma2(a[i][2].y, s2.y, q2);
                            q1 = ffma2(a[i][3].x, s3.x, q1);
                            q2 = ffma2(a[i][3].y, s3.y, q2);
                            float sim = wred(hsum2(fadd2(q1, q2)));
                            accD += fmaxf(0.5f - sim, 0.f);
                        }
                    }
                }
            }
        }
        __syncthreads();
    }

    // block-level combine
    float aWarp = wred(hsum2(accAa) + hsum2(accAb));

    __shared__ float rA[NWARPS], rD[NWARPS];
    __shared__ int   sLast;
    if (lane == 0) { rA[wid] = aWarp; rD[wid] = accD; }
    __syncthreads();
    if (tid == 0) {
        float sA = 0.f, sD = 0.f;
#pragma unroll
        for (int w = 0; w < NWARPS; ++w) { sA += rA[w]; sD += rD[w]; }
        const int bidx = b * NSEG + seg;
        g_part[bidx] = make_float2(sA, sD);
        __threadfence();
        unsigned t = atomicAdd(&g_count, 1u);
        sLast = (t == NBLK - 1);
    }
    __syncthreads();

    // last block performs the deterministic final reduction
    if (sLast && tid < 32) {
        __threadfence();
        const float* gp = reinterpret_cast<const float*>(g_part);
        float a = 0.f, dd = 0.f;
        for (int i = tid; i < NBLK; i += 32) {
            a  += __ldcg(gp + 2 * i);
            dd += __ldcg(gp + 2 * i + 1);
        }
        a  = wred(a);
        dd = wred(dd);
        if (tid == 0) {
            float adj  = 1.f - a / ((float)NB * (float)(SS - 1));
            float dist = dd / ((float)NB * (float)CNT_DIST);
            out[0] = adj + dist;
            g_count = 0;                      // reset for next graph replay
        }
    }
}

extern "C" void kernel_launch(void* const* d_in, const int* in_sizes, int n_in,
                              void* d_out, int out_size) {
    (void)in_sizes; (void)n_in; (void)out_size;
    const float* hs = (const float*)d_in[0];

    const size_t shmem = (size_t)RING * RPAD * sizeof(ulonglong2);  // 171,312 B
    cudaFuncSetAttribute(tcl_main, cudaFuncAttributeMaxDynamicSharedMemorySize,
                         (int)shmem);

    dim3 grid(NSEG, NB);
    tcl_main<<<grid, NTHR, shmem>>>(hs, (float*)d_out);
}

// round 5
// speedup vs baseline: 1.3655x; 1.0089x over previous
#include <cuda_runtime.h>

typedef unsigned long long u64;

#define NB      16
#define SS      4096
#define D4      128          // float4 per row
#define RPAD    129          // padded float4 stride in smem
#define HALO    19
#define CHUNK   64
#define RING    83
#define TM      8
#define NWARPS  8
#define NTHR    256
#define NSEG    9
#define SEGROWS 456          // 8 segs of 456 + last 448 = 4096
#define NBLK    (NB * NSEG)  // 144
#define CNT_DIST 40815       // sum_{k=10}^{19} (4096 - k)

__device__ float2       g_part[NBLK];
__device__ unsigned int g_count = 0;

__device__ __forceinline__ u64 ffma2(u64 a, u64 b, u64 c) {
    u64 d;
    asm("fma.rn.f32x2 %0, %1, %2, %3;" : "=l"(d) : "l"(a), "l"(b), "l"(c));
    return d;
}
__device__ __forceinline__ u64 fmul2(u64 a, u64 b) {
    u64 d;
    asm("mul.rn.f32x2 %0, %1, %2;" : "=l"(d) : "l"(a), "l"(b));
    return d;
}
__device__ __forceinline__ u64 fadd2(u64 a, u64 b) {
    u64 d;
    asm("add.rn.f32x2 %0, %1, %2;" : "=l"(d) : "l"(a), "l"(b));
    return d;
}
__device__ __forceinline__ u64 pack2(float x, float y) {
    u64 d;
    asm("mov.b64 %0, {%1, %2};" : "=l"(d) : "f"(x), "f"(y));
    return d;
}
__device__ __forceinline__ float hsum2(u64 v) {
    float x, y;
    asm("mov.b64 {%0,%1}, %2;" : "=f"(x), "=f"(y) : "l"(v));
    return x + y;
}
__device__ __forceinline__ float wred(float v) {
    v += __shfl_xor_sync(0xffffffffu, v, 16);
    v += __shfl_xor_sync(0xffffffffu, v, 8);
    v += __shfl_xor_sync(0xffffffffu, v, 4);
    v += __shfl_xor_sync(0xffffffffu, v, 2);
    v += __shfl_xor_sync(0xffffffffu, v, 1);
    return v;
}

extern __shared__ ulonglong2 smem[];   // RING rows * RPAD float4 (unit rows)

__global__ void __launch_bounds__(NTHR, 1)
tcl_main(const float* __restrict__ hs, float* __restrict__ out) {
    const int seg  = blockIdx.x;
    const int b    = blockIdx.y;
    const int t0   = seg * SEGROWS;
    const int tEnd = (t0 + SEGROWS < SS) ? (t0 + SEGROWS) : SS;
    const int nch  = (tEnd - t0 + CHUNK - 1) / CHUNK;

    const int tid  = threadIdx.x;
    const int wid  = tid >> 5;
    const int lane = tid & 31;

    const ulonglong2* __restrict__ hb =
        reinterpret_cast<const ulonglong2*>(hs) + (size_t)b * SS * D4;

    u64   accAa = 0ull, accAb = 0ull;  // adjacent sum, packed, reduction-free
    float accD  = 0.f;                 // distant relu sum (lane-replicated)

    for (int ci = 0; ci < nch; ++ci) {
        const int c0     = t0 + ci * CHUNK;
        const int loadLo = ci ? (c0 + HALO) : c0;
        const int loadHi = (c0 + RING < SS) ? (c0 + RING) : SS;

        // ── Phase A: load + normalize. 8 threads per row, 32 rows/pass.
        // MLP-16 loads; squares folded into load stream; 3-shfl group
        // reduction; store with per-slice rotation (i+q)&15 so the 8 slices
        // of a row never collide on banks. The rotation is identical for
        // every row, so all dot products / norms are unaffected.
        for (int r0 = loadLo; r0 < loadHi; r0 += 32) {
            int row  = r0 + (tid >> 3);
            int ok   = row < loadHi;
            int rowc = ok ? row : (loadHi - 1);
            int q    = tid & 7;
            const ulonglong2* __restrict__ src = hb + (size_t)rowc * D4 + q * 16;

            ulonglong2 v[16];
#pragma unroll
            for (int i = 0; i < 16; ++i) v[i] = src[i];

            u64 p0 = 0ull, p1 = 0ull, p2 = 0ull, p3 = 0ull;
#pragma unroll
            for (int i = 0; i < 16; i += 2) {
                p0 = ffma2(v[i].x,   v[i].x,   p0);
                p1 = ffma2(v[i].y,   v[i].y,   p1);
                p2 = ffma2(v[i+1].x, v[i+1].x, p2);
                p3 = ffma2(v[i+1].y, v[i+1].y, p3);
            }
            float s = hsum2(fadd2(fadd2(p0, p1), fadd2(p2, p3)));
            s += __shfl_xor_sync(0xffffffffu, s, 1);
            s += __shfl_xor_sync(0xffffffffu, s, 2);
            s += __shfl_xor_sync(0xffffffffu, s, 4);
            float invn = rsqrtf(s);
            u64 iv = pack2(invn, invn);

            if (ok) {
                int slot = (row - t0) % RING;
                ulonglong2* dst = smem + (size_t)slot * RPAD + q * 16;
#pragma unroll
                for (int i = 0; i < 16; ++i) {
                    ulonglong2 w;
                    w.x = fmul2(v[i].x, iv);
                    w.y = fmul2(v[i].y, iv);
                    dst[(i + q) & 15] = w;
                }
            }
        }
        __syncthreads();

        // ── Phase B: banded dot products on unit rows ────────────────────
        const int rowEnd = (c0 + CHUNK < tEnd) ? (c0 + CHUNK) : tEnd;
        const int tt     = c0 + wid * TM;
        if (tt < rowEnd) {                    // whole 8-row tile valid
            const int sb = (tt - t0) % RING;

            ulonglong2 a[TM][4];
#pragma unroll
            for (int i = 0; i < TM; ++i) {
                int sl = sb + i; if (sl >= RING) sl -= RING;
                const ulonglong2* row = smem + (size_t)sl * RPAD;
#pragma unroll
                for (int j = 0; j < 4; ++j) a[i][j] = row[lane + 32 * j];
            }

#pragma unroll
            for (int d = 1; d <= TM + HALO - 1; ++d) {
                int r = tt + d;
                if (r < SS) {                 // warp-uniform
                    int sl = sb + d; if (sl >= RING) sl -= RING;
                    const ulonglong2* row = smem + (size_t)sl * RPAD;
                    ulonglong2 s0 = row[lane];
                    ulonglong2 s1 = row[lane + 32];
                    ulonglong2 s2 = row[lane + 64];
                    ulonglong2 s3 = row[lane + 96];

                    if (d <= TM) {            // adjacent pair: no reduction
                        const int i = d - 1;
                        accAa = ffma2(a[i][0].x, s0.x, accAa);
                        accAb = ffma2(a[i][0].y, s0.y, accAb);
                        accAa = ffma2(a[i][1].x, s1.x, accAa);
                        accAb = ffma2(a[i][1].y, s1.y, accAb);
                        accAa = ffma2(a[i][2].x, s2.x, accAa);
                        accAb = ffma2(a[i][2].y, s2.y, accAb);
                        accAa = ffma2(a[i][3].x, s3.x, accAa);
                        accAb = ffma2(a[i][3].y, s3.y, accAb);
                    }

#pragma unroll
                    for (int k = 10; k <= 19; ++k) {
                        const int i = d - k;
                        if (0 <= i && i < TM) {   // compile-time pruned
                            u64 q1 = 0ull, q2 = 0ull;
                            q1 = ffma2(a[i][0].x, s0.x, q1);
                            q2 = ffma2(a[i][0].y, s0.y, q2);
                            q1 = ffma2(a[i][1].x, s1.x, q1);
                            q2 = ffma2(a[i][1].y, s1.y, q2);
                            q1 = ffma2(a[i][2].x, s2.x, q1);
                            q2 = ffma2(a[i][2].y, s2.y, q2);
                            q1 = ffma2(a[i][3].x, s3.x, q1);
                            q2 = ffma2(a[i][3].y, s3.y, q2);
                            float sim = wred(hsum2(fadd2(q1, q2)));
                            accD += fmaxf(0.5f - sim, 0.f);
                        }
                    }
                }
            }
        }
        __syncthreads();
    }

    // block-level combine
    float aWarp = wred(hsum2(accAa) + hsum2(accAb));

    __shared__ float rA[NWARPS], rD[NWARPS];
    __shared__ int   sLast;
    if (lane == 0) { rA[wid] = aWarp; rD[wid] = accD; }
    __syncthreads();
    if (tid == 0) {
        float sA = 0.f, sD = 0.f;
#pragma unroll
        for (int w = 0; w < NWARPS; ++w) { sA += rA[w]; sD += rD[w]; }
        const int bidx = b * NSEG + seg;
        g_part[bidx] = make_float2(sA, sD);
        __threadfence();
        unsigned t = atomicAdd(&g_count, 1u);
        sLast = (t == NBLK - 1);
    }
    __syncthreads();

    // last block performs the deterministic final reduction
    if (sLast && tid < 32) {
        __threadfence();
        const float* gp = reinterpret_cast<const float*>(g_part);
        float a = 0.f, dd = 0.f;
        for (int i = tid; i < NBLK; i += 32) {
            a  += __ldcg(gp + 2 * i);
            dd += __ldcg(gp + 2 * i + 1);
        }
        a  = wred(a);
        dd = wred(dd);
        if (tid == 0) {
            float adj  = 1.f - a / ((float)NB * (float)(SS - 1));
            float dist = dd / ((float)NB * (float)CNT_DIST);
            out[0] = adj + dist;
            g_count = 0;                      // reset for next graph replay
        }
    }
}

extern "C" void kernel_launch(void* const* d_in, const int* in_sizes, int n_in,
                              void* d_out, int out_size) {
    (void)in_sizes; (void)n_in; (void)out_size;
    const float* hs = (const float*)d_in[0];

    const size_t shmem = (size_t)RING * RPAD * sizeof(ulonglong2);  // 171,312 B
    cudaFuncSetAttribute(tcl_main, cudaFuncAttributeMaxDynamicSharedMemorySize,
                         (int)shmem);

    dim3 grid(NSEG, NB);
    tcl_main<<<grid, NTHR, shmem>>>(hs, (float*)d_out);
}

// round 6
// speedup vs baseline: 1.8346x; 1.3436x over previous
#include <cuda_runtime.h>

typedef unsigned long long u64;
typedef unsigned int u32;

#define NB      16
#define SS      4096
#define D4      128          // float4 per row
#define ROWB    2048         // bytes per row
#define HALO    19
#define CHUNK   32
#define RING    83           // 2*CHUNK + HALO
#define TM      4
#define NWARPS  8
#define NTHR    256
#define NSEG    9
#define SEGROWS 456          // 8 segs of 456 + last 448 = 4096
#define NBLK    (NB * NSEG)  // 144
#define CNT_DIST 40815       // sum_{k=10}^{19} (4096 - k)

__device__ float2       g_part[NBLK];
__device__ unsigned int g_count = 0;

__device__ __forceinline__ u64 ffma2(u64 a, u64 b, u64 c) {
    u64 d;
    asm("fma.rn.f32x2 %0, %1, %2, %3;" : "=l"(d) : "l"(a), "l"(b), "l"(c));
    return d;
}
__device__ __forceinline__ u64 fmul2(u64 a, u64 b) {
    u64 d;
    asm("mul.rn.f32x2 %0, %1, %2;" : "=l"(d) : "l"(a), "l"(b));
    return d;
}
__device__ __forceinline__ u64 fadd2(u64 a, u64 b) {
    u64 d;
    asm("add.rn.f32x2 %0, %1, %2;" : "=l"(d) : "l"(a), "l"(b));
    return d;
}
__device__ __forceinline__ u64 pack2(float x, float y) {
    u64 d;
    asm("mov.b64 %0, {%1, %2};" : "=l"(d) : "f"(x), "f"(y));
    return d;
}
__device__ __forceinline__ float hsum2(u64 v) {
    float x, y;
    asm("mov.b64 {%0,%1}, %2;" : "=f"(x), "=f"(y) : "l"(v));
    return x + y;
}
__device__ __forceinline__ float wred(float v) {
    v += __shfl_xor_sync(0xffffffffu, v, 16);
    v += __shfl_xor_sync(0xffffffffu, v, 8);
    v += __shfl_xor_sync(0xffffffffu, v, 4);
    v += __shfl_xor_sync(0xffffffffu, v, 2);
    v += __shfl_xor_sync(0xffffffffu, v, 1);
    return v;
}
__device__ __forceinline__ u32 smem_u32(const void* p) {
    u32 a;
    asm("{ .reg .u64 t; cvta.to.shared.u64 t, %1; cvt.u32.u64 %0, t; }"
        : "=r"(a) : "l"(p));
    return a;
}
__device__ __forceinline__ void mbar_init(u32 mbar, u32 cnt) {
    asm volatile("mbarrier.init.shared.b64 [%0], %1;" :: "r"(mbar), "r"(cnt) : "memory");
}
__device__ __forceinline__ void mbar_expect(u32 mbar, u32 bytes) {
    asm volatile("mbarrier.arrive.expect_tx.shared.b64 _, [%0], %1;"
                 :: "r"(mbar), "r"(bytes) : "memory");
}
__device__ __forceinline__ void bulk_g2s(u32 dst, const void* src, u32 bytes, u32 mbar) {
    asm volatile("cp.async.bulk.shared::cta.global.mbarrier::complete_tx::bytes "
                 "[%0], [%1], %2, [%3];"
                 :: "r"(dst), "l"(src), "r"(bytes), "r"(mbar) : "memory");
}
__device__ __forceinline__ void mbar_wait(u32 mbar, u32 parity) {
    asm volatile(
        "{\n\t.reg .pred P;\n"
        "W%=:\n\t"
        "mbarrier.try_wait.parity.acquire.cta.shared::cta.b64 P, [%0], %1, 0x989680;\n\t"
        "@P bra D%=;\n\t"
        "bra W%=;\n"
        "D%=:\n\t}"
        :: "r"(mbar), "r"(parity) : "memory");
}

extern __shared__ ulonglong2 smem[];   // RING*D4 row data, then mbarrier

// normalize one 2KB row in smem to unit length (warp-collective, conflict-free)
__device__ __forceinline__ void norm_row(ulonglong2* rows, int slot, int lane) {
    ulonglong2* row = rows + (size_t)slot * D4;
    ulonglong2 v0 = row[lane];
    ulonglong2 v1 = row[lane + 32];
    ulonglong2 v2 = row[lane + 64];
    ulonglong2 v3 = row[lane + 96];
    u64 p0 = 0ull, p1 = 0ull, p2 = 0ull, p3 = 0ull;
    p0 = ffma2(v0.x, v0.x, p0); p1 = ffma2(v0.y, v0.y, p1);
    p2 = ffma2(v1.x, v1.x, p2); p3 = ffma2(v1.y, v1.y, p3);
    p0 = ffma2(v2.x, v2.x, p0); p1 = ffma2(v2.y, v2.y, p1);
    p2 = ffma2(v3.x, v3.x, p2); p3 = ffma2(v3.y, v3.y, p3);
    float s    = wred(hsum2(fadd2(fadd2(p0, p1), fadd2(p2, p3))));
    float invn = rsqrtf(s);
    u64 iv = pack2(invn, invn);
    v0.x = fmul2(v0.x, iv); v0.y = fmul2(v0.y, iv);
    v1.x = fmul2(v1.x, iv); v1.y = fmul2(v1.y, iv);
    v2.x = fmul2(v2.x, iv); v2.y = fmul2(v2.y, iv);
    v3.x = fmul2(v3.x, iv); v3.y = fmul2(v3.y, iv);
    row[lane]      = v0;
    row[lane + 32] = v1;
    row[lane + 64] = v2;
    row[lane + 96] = v3;
}

__global__ void __launch_bounds__(NTHR, 1)
tcl_main(const float* __restrict__ hs, float* __restrict__ out) {
    const int seg  = blockIdx.x;
    const int b    = blockIdx.y;
    const int t0   = seg * SEGROWS;
    const int tEnd = (t0 + SEGROWS < SS) ? (t0 + SEGROWS) : SS;
    const int rEnd = (tEnd + HALO < SS) ? (tEnd + HALO) : SS;   // rows needed
    const int tid  = threadIdx.x;
    const int wid  = tid >> 5;
    const int lane = tid & 31;

    ulonglong2* rows = smem;
    const char* gbase = reinterpret_cast<const char*>(hs) + (size_t)b * SS * ROWB;
    const u32 sbase = smem_u32(smem);
    const u32 mbar  = sbase + RING * ROWB;

    // ── prologue: bulk-load the first 83 rows, normalize them ────────────
    if (tid == 0) {
        mbar_init(mbar, 1);
        asm volatile("fence.proxy.async.shared::cta;" ::: "memory");
    }
    __syncthreads();
    if (tid == 0) {
        mbar_expect(mbar, RING * ROWB);
        bulk_g2s(sbase, gbase + (size_t)t0 * ROWB, RING * ROWB, mbar);
    }
    mbar_wait(mbar, 0);
    for (int r = wid; r < RING; r += NWARPS) norm_row(rows, r, lane);
    __syncthreads();

    u64   accAa = 0ull, accAb = 0ull;  // adjacent sum (linear, packed)
    float accD  = 0.f;                 // distant relu sum (lane-replicated)

    const int nsteps = (tEnd - t0 + CHUNK - 1) / CHUNK;

    for (int i = 0; i < nsteps; ++i) {
        const int c0     = t0 + CHUNK * i;
        const int rowEnd = (c0 + CHUNK < tEnd) ? (c0 + CHUNK) : tEnd;
        const int tt     = c0 + wid * TM;

        // ── Phase B: pairs for this 32-row chunk ─────────────────────────
        if (tt < rowEnd) {                       // warp-uniform; tiles 4-aligned
            int sb = (tt - t0) % RING;

            ulonglong2 a[TM][4];
#pragma unroll
            for (int ii = 0; ii < TM; ++ii) {
                int sl = sb + ii; if (sl >= RING) sl -= RING;
                const ulonglong2* row = rows + (size_t)sl * D4;
#pragma unroll
                for (int j = 0; j < 4; ++j) a[ii][j] = row[lane + 32 * j];
            }

            // adjacent pairs with both rows in registers: i = 0..2
#pragma unroll
            for (int ii = 0; ii < TM - 1; ++ii) {
                accAa = ffma2(a[ii][0].x, a[ii+1][0].x, accAa);
                accAb = ffma2(a[ii][0].y, a[ii+1][0].y, accAb);
                accAa = ffma2(a[ii][1].x, a[ii+1][1].x, accAa);
                accAb = ffma2(a[ii][1].y, a[ii+1][1].y, accAb);
                accAa = ffma2(a[ii][2].x, a[ii+1][2].x, accAa);
                accAb = ffma2(a[ii][2].y, a[ii+1][2].y, accAb);
                accAa = ffma2(a[ii][3].x, a[ii+1][3].x, accAa);
                accAb = ffma2(a[ii][3].y, a[ii+1][3].y, accAb);
            }

            // adjacent pair i = 3 (partner = row tt+4 from smem)
            {
                int r = tt + TM;
                if (r < rEnd) {
                    int sl = sb + TM; if (sl >= RING) sl -= RING;
                    const ulonglong2* row = rows + (size_t)sl * D4;
                    ulonglong2 s0 = row[lane];
                    ulonglong2 s1 = row[lane + 32];
                    ulonglong2 s2 = row[lane + 64];
                    ulonglong2 s3 = row[lane + 96];
                    accAa = ffma2(a[3][0].x, s0.x, accAa);
                    accAb = ffma2(a[3][0].y, s0.y, accAb);
                    accAa = ffma2(a[3][1].x, s1.x, accAa);
                    accAb = ffma2(a[3][1].y, s1.y, accAb);
                    accAa = ffma2(a[3][2].x, s2.x, accAa);
                    accAb = ffma2(a[3][2].y, s2.y, accAb);
                    accAa = ffma2(a[3][3].x, s3.x, accAa);
                    accAb = ffma2(a[3][3].y, s3.y, accAb);
                }
            }

            // distant pairs: partner rows d = 10..22 only
#pragma unroll
            for (int d = 10; d <= TM + HALO - 1; ++d) {
                int r = tt + d;
                if (r < rEnd) {                  // warp-uniform
                    int sl = sb + d; if (sl >= RING) sl -= RING;
                    const ulonglong2* row = rows + (size_t)sl * D4;
                    ulonglong2 s0 = row[lane];
                    ulonglong2 s1 = row[lane + 32];
                    ulonglong2 s2 = row[lane + 64];
                    ulonglong2 s3 = row[lane + 96];
#pragma unroll
                    for (int k = 10; k <= 19; ++k) {
                        const int ii = d - k;
                        if (0 <= ii && ii < TM) {    // compile-time pruned
                            u64 q1 = 0ull, q2 = 0ull;
                            q1 = ffma2(a[ii][0].x, s0.x, q1);
                            q2 = ffma2(a[ii][0].y, s0.y, q2);
                            q1 = ffma2(a[ii][1].x, s1.x, q1);
                            q2 = ffma2(a[ii][1].y, s1.y, q2);
                            q1 = ffma2(a[ii][2].x, s2.x, q1);
                            q2 = ffma2(a[ii][2].y, s2.y, q2);
                            q1 = ffma2(a[ii][3].x, s3.x, q1);
                            q2 = ffma2(a[ii][3].y, s3.y, q2);
                            float sim = wred(hsum2(fadd2(q1, q2)));
                            accD += fmaxf(0.5f - sim, 0.f);
                        }
                    }
                }
            }
        }

        // ── wait for copy C_i (issued last step), normalize its rows ─────
        if (i >= 1) {
            int cs = t0 + (RING - CHUNK) + CHUNK * i;   // t0 + 51 + 32i
            if (cs < rEnd) {
                mbar_wait(mbar, (u32)(i & 1));
                int ce = (cs + CHUNK < rEnd) ? (cs + CHUNK) : rEnd;
                for (int r = cs + wid; r < ce; r += NWARPS)
                    norm_row(rows, (r - t0) % RING, lane);
            }
        }
        __syncthreads();

        // ── issue copy C_{i+1}: overwrites this step's tile slots (safe) ─
        if (tid == 0) {
            int ns = t0 + (RING - CHUNK) + CHUNK * (i + 1);
            if (ns < rEnd) {
                int ne = (ns + CHUNK < rEnd) ? (ns + CHUNK) : rEnd;
                u32 bytes = (u32)(ne - ns) * ROWB;
                mbar_expect(mbar, bytes);
                int s0  = (ns - t0) % RING;
                int len = ne - ns;
                int l1  = (RING - s0 < len) ? (RING - s0) : len;
                bulk_g2s(sbase + (u32)s0 * ROWB, gbase + (size_t)ns * ROWB,
                         (u32)l1 * ROWB, mbar);
                if (l1 < len)
                    bulk_g2s(sbase, gbase + (size_t)(ns + l1) * ROWB,
                             (u32)(len - l1) * ROWB, mbar);
            }
        }
    }

    // ── block combine + grid ticket reduction ───────────────────────────
    float aWarp = wred(hsum2(accAa) + hsum2(accAb));

    __shared__ float rA[NWARPS], rD[NWARPS];
    __shared__ int   sLast;
    if (lane == 0) { rA[wid] = aWarp; rD[wid] = accD; }
    __syncthreads();
    if (tid == 0) {
        float sA = 0.f, sD = 0.f;
#pragma unroll
        for (int w = 0; w < NWARPS; ++w) { sA += rA[w]; sD += rD[w]; }
        g_part[b * NSEG + seg] = make_float2(sA, sD);
        __threadfence();
        unsigned t = atomicAdd(&g_count, 1u);
        sLast = (t == NBLK - 1);
    }
    __syncthreads();

    if (sLast && tid < 32) {
        __threadfence();
        const float* gp = reinterpret_cast<const float*>(g_part);
        float a = 0.f, dd = 0.f;
        for (int i = tid; i < NBLK; i += 32) {
            a  += __ldcg(gp + 2 * i);
            dd += __ldcg(gp + 2 * i + 1);
        }
        a  = wred(a);
        dd = wred(dd);
        if (tid == 0) {
            float adj  = 1.f - a / ((float)NB * (float)(SS - 1));
            float dist = dd / ((float)NB * (float)CNT_DIST);
            out[0] = adj + dist;
            g_count = 0;                      // reset for next graph replay
        }
    }
}

extern "C" void kernel_launch(void* const* d_in, const int* in_sizes, int n_in,
                              void* d_out, int out_size) {
    (void)in_sizes; (void)n_in; (void)out_size;
    const float* hs = (const float*)d_in[0];

    const size_t shmem = (size_t)RING * ROWB + 16;   // rows + mbarrier
    cudaFuncSetAttribute(tcl_main, cudaFuncAttributeMaxDynamicSharedMemorySize,
                         (int)shmem);

    dim3 grid(NSEG, NB);
    tcl_main<<<grid, NTHR, shmem>>>(hs, (float*)d_out);
}

// round 7
// speedup vs baseline: 1.9635x; 1.0703x over previous
#include <cuda_runtime.h>

typedef unsigned long long u64;
typedef unsigned int u32;

#define NB      16
#define SS      4096
#define D4      128          // float4 per row
#define ROWB    2048         // bytes per row
#define HALO    19
#define CHUNK   32
#define RING    83           // 2*CHUNK + HALO
#define TM      2
#define NWARPS  16
#define NTHR    512
#define NSEG    9
#define SEGROWS 456          // 8 segs of 456 + last 448 = 4096
#define NBLK    (NB * NSEG)  // 144
#define CNT_DIST 40815       // sum_{k=10}^{19} (4096 - k)

__device__ float2       g_part[NBLK];
__device__ unsigned int g_count = 0;

__device__ __forceinline__ u64 ffma2(u64 a, u64 b, u64 c) {
    u64 d;
    asm("fma.rn.f32x2 %0, %1, %2, %3;" : "=l"(d) : "l"(a), "l"(b), "l"(c));
    return d;
}
__device__ __forceinline__ u64 fmul2(u64 a, u64 b) {
    u64 d;
    asm("mul.rn.f32x2 %0, %1, %2;" : "=l"(d) : "l"(a), "l"(b));
    return d;
}
__device__ __forceinline__ u64 fadd2(u64 a, u64 b) {
    u64 d;
    asm("add.rn.f32x2 %0, %1, %2;" : "=l"(d) : "l"(a), "l"(b));
    return d;
}
__device__ __forceinline__ u64 pack2(float x, float y) {
    u64 d;
    asm("mov.b64 %0, {%1, %2};" : "=l"(d) : "f"(x), "f"(y));
    return d;
}
__device__ __forceinline__ float hsum2(u64 v) {
    float x, y;
    asm("mov.b64 {%0,%1}, %2;" : "=f"(x), "=f"(y) : "l"(v));
    return x + y;
}
__device__ __forceinline__ float wred(float v) {
    v += __shfl_xor_sync(0xffffffffu, v, 16);
    v += __shfl_xor_sync(0xffffffffu, v, 8);
    v += __shfl_xor_sync(0xffffffffu, v, 4);
    v += __shfl_xor_sync(0xffffffffu, v, 2);
    v += __shfl_xor_sync(0xffffffffu, v, 1);
    return v;
}
__device__ __forceinline__ u32 smem_u32(const void* p) {
    u32 a;
    asm("{ .reg .u64 t; cvta.to.shared.u64 t, %1; cvt.u32.u64 %0, t; }"
        : "=r"(a) : "l"(p));
    return a;
}
__device__ __forceinline__ void mbar_init(u32 mbar, u32 cnt) {
    asm volatile("mbarrier.init.shared.b64 [%0], %1;" :: "r"(mbar), "r"(cnt) : "memory");
}
__device__ __forceinline__ void mbar_expect(u32 mbar, u32 bytes) {
    asm volatile("mbarrier.arrive.expect_tx.shared.b64 _, [%0], %1;"
                 :: "r"(mbar), "r"(bytes) : "memory");
}
__device__ __forceinline__ void bulk_g2s(u32 dst, const void* src, u32 bytes, u32 mbar) {
    asm volatile("cp.async.bulk.shared::cta.global.mbarrier::complete_tx::bytes "
                 "[%0], [%1], %2, [%3];"
                 :: "r"(dst), "l"(src), "r"(bytes), "r"(mbar) : "memory");
}
__device__ __forceinline__ void mbar_wait(u32 mbar, u32 parity) {
    asm volatile(
        "{\n\t.reg .pred P;\n"
        "W%=:\n\t"
        "mbarrier.try_wait.parity.acquire.cta.shared::cta.b64 P, [%0], %1, 0x989680;\n\t"
        "@P bra D%=;\n\t"
        "bra W%=;\n"
        "D%=:\n\t}"
        :: "r"(mbar), "r"(parity) : "memory");
}

extern __shared__ ulonglong2 smem[];   // RING*D4 row data, then mbarrier

// normalize one 2KB row in smem to unit length (warp-collective, conflict-free)
__device__ __forceinline__ void norm_row(ulonglong2* rows, int slot, int lane) {
    ulonglong2* row = rows + (size_t)slot * D4;
    ulonglong2 v0 = row[lane];
    ulonglong2 v1 = row[lane + 32];
    ulonglong2 v2 = row[lane + 64];
    ulonglong2 v3 = row[lane + 96];
    u64 p0 = 0ull, p1 = 0ull, p2 = 0ull, p3 = 0ull;
    p0 = ffma2(v0.x, v0.x, p0); p1 = ffma2(v0.y, v0.y, p1);
    p2 = ffma2(v1.x, v1.x, p2); p3 = ffma2(v1.y, v1.y, p3);
    p0 = ffma2(v2.x, v2.x, p0); p1 = ffma2(v2.y, v2.y, p1);
    p2 = ffma2(v3.x, v3.x, p2); p3 = ffma2(v3.y, v3.y, p3);
    float s    = wred(hsum2(fadd2(fadd2(p0, p1), fadd2(p2, p3))));
    float invn = rsqrtf(s);
    u64 iv = pack2(invn, invn);
    v0.x = fmul2(v0.x, iv); v0.y = fmul2(v0.y, iv);
    v1.x = fmul2(v1.x, iv); v1.y = fmul2(v1.y, iv);
    v2.x = fmul2(v2.x, iv); v2.y = fmul2(v2.y, iv);
    v3.x = fmul2(v3.x, iv); v3.y = fmul2(v3.y, iv);
    row[lane]      = v0;
    row[lane + 32] = v1;
    row[lane + 64] = v2;
    row[lane + 96] = v3;
}

__global__ void __launch_bounds__(NTHR, 1)
tcl_main(const float* __restrict__ hs, float* __restrict__ out) {
    const int seg  = blockIdx.x;
    const int b    = blockIdx.y;
    const int t0   = seg * SEGROWS;
    const int tEnd = (t0 + SEGROWS < SS) ? (t0 + SEGROWS) : SS;
    const int rEnd = (tEnd + HALO < SS) ? (tEnd + HALO) : SS;   // rows needed
    const int tid  = threadIdx.x;
    const int wid  = tid >> 5;
    const int lane = tid & 31;

    ulonglong2* rows = smem;
    const char* gbase = reinterpret_cast<const char*>(hs) + (size_t)b * SS * ROWB;
    const u32 sbase = smem_u32(smem);
    const u32 mbar  = sbase + RING * ROWB;

    // ── prologue: bulk-load the first 83 rows, normalize them ────────────
    if (tid == 0) {
        mbar_init(mbar, 1);
        asm volatile("fence.proxy.async.shared::cta;" ::: "memory");
    }
    __syncthreads();
    if (tid == 0) {
        mbar_expect(mbar, RING * ROWB);
        bulk_g2s(sbase, gbase + (size_t)t0 * ROWB, RING * ROWB, mbar);
    }
    mbar_wait(mbar, 0);
    for (int r = wid; r < RING; r += NWARPS) norm_row(rows, r, lane);
    __syncthreads();

    u64   accAa = 0ull, accAb = 0ull;  // adjacent sum (linear, packed)
    float accD  = 0.f;                 // distant relu sum (lane-replicated)

    const int nsteps = (tEnd - t0 + CHUNK - 1) / CHUNK;

    for (int i = 0; i < nsteps; ++i) {
        const int c0     = t0 + CHUNK * i;
        const int rowEnd = (c0 + CHUNK < tEnd) ? (c0 + CHUNK) : tEnd;
        const int tt     = c0 + wid * TM;

        // ── Phase B: pairs for this 32-row chunk (16 warps × 2 rows) ────
        if (tt < rowEnd) {                       // warp-uniform; tiles 2-aligned
            int sb = (tt - t0) % RING;

            ulonglong2 a[TM][4];
#pragma unroll
            for (int ii = 0; ii < TM; ++ii) {
                int sl = sb + ii; if (sl >= RING) sl -= RING;
                const ulonglong2* row = rows + (size_t)sl * D4;
#pragma unroll
                for (int j = 0; j < 4; ++j) a[ii][j] = row[lane + 32 * j];
            }

            // adjacent pair (tt, tt+1): both rows in registers
            accAa = ffma2(a[0][0].x, a[1][0].x, accAa);
            accAb = ffma2(a[0][0].y, a[1][0].y, accAb);
            accAa = ffma2(a[0][1].x, a[1][1].x, accAa);
            accAb = ffma2(a[0][1].y, a[1][1].y, accAb);
            accAa = ffma2(a[0][2].x, a[1][2].x, accAa);
            accAb = ffma2(a[0][2].y, a[1][2].y, accAb);
            accAa = ffma2(a[0][3].x, a[1][3].x, accAa);
            accAb = ffma2(a[0][3].y, a[1][3].y, accAb);

            // adjacent pair (tt+1, tt+2): partner row d = 2 from smem
            {
                int r = tt + TM;
                if (r < rEnd) {
                    int sl = sb + TM; if (sl >= RING) sl -= RING;
                    const ulonglong2* row = rows + (size_t)sl * D4;
                    ulonglong2 s0 = row[lane];
                    ulonglong2 s1 = row[lane + 32];
                    ulonglong2 s2 = row[lane + 64];
                    ulonglong2 s3 = row[lane + 96];
                    accAa = ffma2(a[1][0].x, s0.x, accAa);
                    accAb = ffma2(a[1][0].y, s0.y, accAb);
                    accAa = ffma2(a[1][1].x, s1.x, accAa);
                    accAb = ffma2(a[1][1].y, s1.y, accAb);
                    accAa = ffma2(a[1][2].x, s2.x, accAa);
                    accAb = ffma2(a[1][2].y, s2.y, accAb);
                    accAa = ffma2(a[1][3].x, s3.x, accAa);
                    accAb = ffma2(a[1][3].y, s3.y, accAb);
                }
            }

            // distant pairs: partner rows d = 10..20
#pragma unroll
            for (int d = 10; d <= TM + HALO - 1; ++d) {
                int r = tt + d;
                if (r < rEnd) {                  // warp-uniform
                    int sl = sb + d; if (sl >= RING) sl -= RING;
                    const ulonglong2* row = rows + (size_t)sl * D4;
                    ulonglong2 s0 = row[lane];
                    ulonglong2 s1 = row[lane + 32];
                    ulonglong2 s2 = row[lane + 64];
                    ulonglong2 s3 = row[lane + 96];
#pragma unroll
                    for (int k = 10; k <= 19; ++k) {
                        const int ii = d - k;
                        if (0 <= ii && ii < TM) {    // compile-time pruned
                            u64 q1 = 0ull, q2 = 0ull;
                            q1 = ffma2(a[ii][0].x, s0.x, q1);
                            q2 = ffma2(a[ii][0].y, s0.y, q2);
                            q1 = ffma2(a[ii][1].x, s1.x, q1);
                            q2 = ffma2(a[ii][1].y, s1.y, q2);
                            q1 = ffma2(a[ii][2].x, s2.x, q1);
                            q2 = ffma2(a[ii][2].y, s2.y, q2);
                            q1 = ffma2(a[ii][3].x, s3.x, q1);
                            q2 = ffma2(a[ii][3].y, s3.y, q2);
                            float sim = wred(hsum2(fadd2(q1, q2)));
                            accD += fmaxf(0.5f - sim, 0.f);
                        }
                    }
                }
            }
        }

        // ── wait for copy C_i (issued last step), normalize its rows ─────
        if (i >= 1) {
            int cs = t0 + (RING - CHUNK) + CHUNK * i;   // t0 + 51 + 32i
            if (cs < rEnd) {
                mbar_wait(mbar, (u32)(i & 1));
                int ce = (cs + CHUNK < rEnd) ? (cs + CHUNK) : rEnd;
                for (int r = cs + wid; r < ce; r += NWARPS)
                    norm_row(rows, (r - t0) % RING, lane);
            }
        }
        __syncthreads();

        // ── issue copy C_{i+1}: overwrites this step's tile slots (safe) ─
        if (tid == 0) {
            int ns = t0 + (RING - CHUNK) + CHUNK * (i + 1);
            if (ns < rEnd) {
                int ne = (ns + CHUNK < rEnd) ? (ns + CHUNK) : rEnd;
                u32 bytes = (u32)(ne - ns) * ROWB;
                mbar_expect(mbar, bytes);
                int s0  = (ns - t0) % RING;
                int len = ne - ns;
                int l1  = (RING - s0 < len) ? (RING - s0) : len;
                bulk_g2s(sbase + (u32)s0 * ROWB, gbase + (size_t)ns * ROWB,
                         (u32)l1 * ROWB, mbar);
                if (l1 < len)
                    bulk_g2s(sbase, gbase + (size_t)(ns + l1) * ROWB,
                             (u32)(len - l1) * ROWB, mbar);
            }
        }
    }

    // ── block combine + grid ticket reduction ───────────────────────────
    float aWarp = wred(hsum2(accAa) + hsum2(accAb));

    __shared__ float rA[NWARPS], rD[NWARPS];
    __shared__ int   sLast;
    if (lane == 0) { rA[wid] = aWarp; rD[wid] = accD; }
    __syncthreads();
    if (tid == 0) {
        float sA = 0.f, sD = 0.f;
#pragma unroll
        for (int w = 0; w < NWARPS; ++w) { sA += rA[w]; sD += rD[w]; }
        g_part[b * NSEG + seg] = make_float2(sA, sD);
        __threadfence();
        unsigned t = atomicAdd(&g_count, 1u);
        sLast = (t == NBLK - 1);
    }
    __syncthreads();

    if (sLast && tid < 32) {
        __threadfence();
        const float* gp = reinterpret_cast<const float*>(g_part);
        float a = 0.f, dd = 0.f;
        for (int i = tid; i < NBLK; i += 32) {
            a  += __ldcg(gp + 2 * i);
            dd += __ldcg(gp + 2 * i + 1);
        }
        a  = wred(a);
        dd = wred(dd);
        if (tid == 0) {
            float adj  = 1.f - a / ((float)NB * (float)(SS - 1));
            float dist = dd / ((float)NB * (float)CNT_DIST);
            out[0] = adj + dist;
            g_count = 0;                      // reset for next graph replay
        }
    }
}

extern "C" void kernel_launch(void* const* d_in, const int* in_sizes, int n_in,
                              void* d_out, int out_size) {
    (void)in_sizes; (void)n_in; (void)out_size;
    const float* hs = (const float*)d_in[0];

    const size_t shmem = (size_t)RING * ROWB + 16;   // rows + mbarrier
    cudaFuncSetAttribute(tcl_main, cudaFuncAttributeMaxDynamicSharedMemorySize,
                         (int)shmem);

    dim3 grid(NSEG, NB);
    tcl_main<<<grid, NTHR, shmem>>>(hs, (float*)d_out);
}

// round 8
// speedup vs baseline: 2.4679x; 1.2569x over previous
#include <cuda_runtime.h>

typedef unsigned long long u64;
typedef unsigned int u32;

#define NB      16
#define SS      4096
#define D4      128          // float4 per row
#define ROWB    2048         // bytes per row
#define HALO    19
#define CHUNK   32
#define RING    83           // 2*CHUNK + HALO
#define TM      2
#define NWARPS  16
#define NTHR    512
#define NSEG    9
#define SEGROWS 456          // 8 segs of 456 + last 448 = 4096
#define NBLK    (NB * NSEG)  // 144
#define CNT_DIST 40815       // sum_{k=10}^{19} (4096 - k)

__device__ float2       g_part[NBLK];
__device__ unsigned int g_count = 0;

__device__ __forceinline__ u64 ffma2(u64 a, u64 b, u64 c) {
    u64 d;
    asm("fma.rn.f32x2 %0, %1, %2, %3;" : "=l"(d) : "l"(a), "l"(b), "l"(c));
    return d;
}
__device__ __forceinline__ u64 fmul2(u64 a, u64 b) {
    u64 d;
    asm("mul.rn.f32x2 %0, %1, %2;" : "=l"(d) : "l"(a), "l"(b));
    return d;
}
__device__ __forceinline__ u64 fadd2(u64 a, u64 b) {
    u64 d;
    asm("add.rn.f32x2 %0, %1, %2;" : "=l"(d) : "l"(a), "l"(b));
    return d;
}
__device__ __forceinline__ u64 pack2(float x, float y) {
    u64 d;
    asm("mov.b64 %0, {%1, %2};" : "=l"(d) : "f"(x), "f"(y));
    return d;
}
__device__ __forceinline__ float hsum2(u64 v) {
    float x, y;
    asm("mov.b64 {%0,%1}, %2;" : "=f"(x), "=f"(y) : "l"(v));
    return x + y;
}
__device__ __forceinline__ float wred(float v) {
    v += __shfl_xor_sync(0xffffffffu, v, 16);
    v += __shfl_xor_sync(0xffffffffu, v, 8);
    v += __shfl_xor_sync(0xffffffffu, v, 4);
    v += __shfl_xor_sync(0xffffffffu, v, 2);
    v += __shfl_xor_sync(0xffffffffu, v, 1);
    return v;
}
// Batched butterfly: reduce 4 per-lane partials across the warp with 6 shfl.
// Result: lane octet g (lane>>3) holds the warp total of v_g (replicated).
__device__ __forceinline__ float bfly4(float v0, float v1, float v2, float v3,
                                       int lane) {
    const bool hi16 = (lane & 16) != 0;
    const bool hi8  = (lane & 8)  != 0;
    float a  = hi16 ? v0 : v2;
    float ra = __shfl_xor_sync(0xffffffffu, a, 16);
    float x  = (hi16 ? v2 : v0) + ra;
    float bb = hi16 ? v1 : v3;
    float rb = __shfl_xor_sync(0xffffffffu, bb, 16);
    float y  = (hi16 ? v3 : v1) + rb;
    float c  = hi8 ? x : y;
    float rc = __shfl_xor_sync(0xffffffffu, c, 8);
    float z  = (hi8 ? y : x) + rc;
    z += __shfl_xor_sync(0xffffffffu, z, 4);
    z += __shfl_xor_sync(0xffffffffu, z, 2);
    z += __shfl_xor_sync(0xffffffffu, z, 1);
    return z;
}
__device__ __forceinline__ u32 smem_u32(const void* p) {
    u32 a;
    asm("{ .reg .u64 t; cvta.to.shared.u64 t, %1; cvt.u32.u64 %0, t; }"
        : "=r"(a) : "l"(p));
    return a;
}
__device__ __forceinline__ void mbar_init(u32 mbar, u32 cnt) {
    asm volatile("mbarrier.init.shared.b64 [%0], %1;" :: "r"(mbar), "r"(cnt) : "memory");
}
__device__ __forceinline__ void mbar_expect(u32 mbar, u32 bytes) {
    asm volatile("mbarrier.arrive.expect_tx.shared.b64 _, [%0], %1;"
                 :: "r"(mbar), "r"(bytes) : "memory");
}
__device__ __forceinline__ void bulk_g2s(u32 dst, const void* src, u32 bytes, u32 mbar) {
    asm volatile("cp.async.bulk.shared::cta.global.mbarrier::complete_tx::bytes "
                 "[%0], [%1], %2, [%3];"
                 :: "r"(dst), "l"(src), "r"(bytes), "r"(mbar) : "memory");
}
__device__ __forceinline__ void mbar_wait(u32 mbar, u32 parity) {
    asm volatile(
        "{\n\t.reg .pred P;\n"
        "W%=:\n\t"
        "mbarrier.try_wait.parity.acquire.cta.shared::cta.b64 P, [%0], %1, 0x989680;\n\t"
        "@P bra D%=;\n\t"
        "bra W%=;\n"
        "D%=:\n\t}"
        :: "r"(mbar), "r"(parity) : "memory");
}

extern __shared__ ulonglong2 smem[];   // RING*D4 row data, then mbarrier

// normalize one 2KB row in smem to unit length (warp-collective, conflict-free)
__device__ __forceinline__ void norm_row(ulonglong2* rows, int slot, int lane) {
    ulonglong2* row = rows + (size_t)slot * D4;
    ulonglong2 v0 = row[lane];
    ulonglong2 v1 = row[lane + 32];
    ulonglong2 v2 = row[lane + 64];
    ulonglong2 v3 = row[lane + 96];
    u64 p0 = 0ull, p1 = 0ull, p2 = 0ull, p3 = 0ull;
    p0 = ffma2(v0.x, v0.x, p0); p1 = ffma2(v0.y, v0.y, p1);
    p2 = ffma2(v1.x, v1.x, p2); p3 = ffma2(v1.y, v1.y, p3);
    p0 = ffma2(v2.x, v2.x, p0); p1 = ffma2(v2.y, v2.y, p1);
    p2 = ffma2(v3.x, v3.x, p2); p3 = ffma2(v3.y, v3.y, p3);
    float s    = wred(hsum2(fadd2(fadd2(p0, p1), fadd2(p2, p3))));
    float invn = rsqrtf(s);
    u64 iv = pack2(invn, invn);
    v0.x = fmul2(v0.x, iv); v0.y = fmul2(v0.y, iv);
    v1.x = fmul2(v1.x, iv); v1.y = fmul2(v1.y, iv);
    v2.x = fmul2(v2.x, iv); v2.y = fmul2(v2.y, iv);
    v3.x = fmul2(v3.x, iv); v3.y = fmul2(v3.y, iv);
    row[lane]      = v0;
    row[lane + 32] = v1;
    row[lane + 64] = v2;
    row[lane + 96] = v3;
}

// pair j -> partner distance d (j enumerates (d, ii) in the fixed order below)
__device__ __forceinline__ int pair_d(int j) {
    return (j == 0) ? 10 : ((j == 19) ? 20 : (10 + ((j + 1) >> 1)));
}

__global__ void __launch_bounds__(NTHR, 1)
tcl_main(const float* __restrict__ hs, float* __restrict__ out) {
    const int seg  = blockIdx.x;
    const int b    = blockIdx.y;
    const int t0   = seg * SEGROWS;
    const int tEnd = (t0 + SEGROWS < SS) ? (t0 + SEGROWS) : SS;
    const int rEnd = (tEnd + HALO < SS) ? (tEnd + HALO) : SS;   // rows needed
    const int tid  = threadIdx.x;
    const int wid  = tid >> 5;
    const int lane = tid & 31;

    ulonglong2* rows = smem;
    const char* gbase = reinterpret_cast<const char*>(hs) + (size_t)b * SS * ROWB;
    const u32 sbase = smem_u32(smem);
    const u32 mbar  = sbase + RING * ROWB;

    // ── prologue: bulk-load the first 83 rows, normalize them ────────────
    if (tid == 0) {
        mbar_init(mbar, 1);
        asm volatile("fence.proxy.async.shared::cta;" ::: "memory");
    }
    __syncthreads();
    if (tid == 0) {
        mbar_expect(mbar, RING * ROWB);
        bulk_g2s(sbase, gbase + (size_t)t0 * ROWB, RING * ROWB, mbar);
    }
    mbar_wait(mbar, 0);
    for (int r = wid; r < RING; r += NWARPS) norm_row(rows, r, lane);
    __syncthreads();

    u64   accAa = 0ull, accAb = 0ull;  // adjacent sum (linear, packed)
    float accD  = 0.f;                 // distant relu sum (per-lane, octet-replicated)

    const int nsteps = (tEnd - t0 + CHUNK - 1) / CHUNK;

    for (int i = 0; i < nsteps; ++i) {
        const int c0     = t0 + CHUNK * i;
        const int rowEnd = (c0 + CHUNK < tEnd) ? (c0 + CHUNK) : tEnd;
        const int tt     = c0 + wid * TM;

        // ── Phase B: pairs for this 32-row chunk (16 warps × 2 rows) ────
        if (tt < rowEnd) {                       // warp-uniform; tiles 2-aligned
            int sb = (tt - t0) % RING;

            ulonglong2 a[TM][4];
#pragma unroll
            for (int ii = 0; ii < TM; ++ii) {
                int sl = sb + ii; if (sl >= RING) sl -= RING;
                const ulonglong2* row = rows + (size_t)sl * D4;
#pragma unroll
                for (int j = 0; j < 4; ++j) a[ii][j] = row[lane + 32 * j];
            }

            // adjacent pair (tt, tt+1): both rows in registers
            accAa = ffma2(a[0][0].x, a[1][0].x, accAa);
            accAb = ffma2(a[0][0].y, a[1][0].y, accAb);
            accAa = ffma2(a[0][1].x, a[1][1].x, accAa);
            accAb = ffma2(a[0][1].y, a[1][1].y, accAb);
            accAa = ffma2(a[0][2].x, a[1][2].x, accAa);
            accAb = ffma2(a[0][2].y, a[1][2].y, accAb);
            accAa = ffma2(a[0][3].x, a[1][3].x, accAa);
            accAb = ffma2(a[0][3].y, a[1][3].y, accAb);

            // adjacent pair (tt+1, tt+2): partner row d = 2 from smem
            {
                int r = tt + TM;
                if (r < rEnd) {
                    int sl = sb + TM; if (sl >= RING) sl -= RING;
                    const ulonglong2* row = rows + (size_t)sl * D4;
                    ulonglong2 s0 = row[lane];
                    ulonglong2 s1 = row[lane + 32];
                    ulonglong2 s2 = row[lane + 64];
                    ulonglong2 s3 = row[lane + 96];
                    accAa = ffma2(a[1][0].x, s0.x, accAa);
                    accAb = ffma2(a[1][0].y, s0.y, accAb);
                    accAa = ffma2(a[1][1].x, s1.x, accAa);
                    accAb = ffma2(a[1][1].y, s1.y, accAb);
                    accAa = ffma2(a[1][2].x, s2.x, accAa);
                    accAb = ffma2(a[1][2].y, s2.y, accAb);
                    accAa = ffma2(a[1][3].x, s3.x, accAa);
                    accAb = ffma2(a[1][3].y, s3.y, accAb);
                }
            }

            // distant pairs: accumulate 20 per-lane partial dots, reduce later.
            // pair order: (d=10,ii=0)=0; (d,ii=0)=2(d-10)-1, (d,ii=1)=2(d-10)
            // for d=11..19; (d=20,ii=1)=19.
            float p[20];
#pragma unroll
            for (int j = 0; j < 20; ++j) p[j] = 0.f;

#pragma unroll
            for (int d = 10; d <= TM + HALO - 1; ++d) {
                int r = tt + d;
                if (r < rEnd) {                  // warp-uniform
                    int sl = sb + d; if (sl >= RING) sl -= RING;
                    const ulonglong2* row = rows + (size_t)sl * D4;
                    ulonglong2 s0 = row[lane];
                    ulonglong2 s1 = row[lane + 32];
                    ulonglong2 s2 = row[lane + 64];
                    ulonglong2 s3 = row[lane + 96];
#pragma unroll
                    for (int ii = 0; ii < TM; ++ii) {
                        const int k = d - ii;
                        if (k >= 10 && k <= 19) {    // compile-time pruned
                            const int j = (d == 10) ? 0
                                        : ((d == 20) ? 19 : (2 * (d - 10) - 1 + ii));
                            u64 q1 = 0ull, q2 = 0ull;
                            q1 = ffma2(a[ii][0].x, s0.x, q1);
                            q2 = ffma2(a[ii][0].y, s0.y, q2);
                            q1 = ffma2(a[ii][1].x, s1.x, q1);
                            q2 = ffma2(a[ii][1].y, s1.y, q2);
                            q1 = ffma2(a[ii][2].x, s2.x, q1);
                            q2 = ffma2(a[ii][2].y, s2.y, q2);
                            q1 = ffma2(a[ii][3].x, s3.x, q1);
                            q2 = ffma2(a[ii][3].y, s3.y, q2);
                            p[j] = hsum2(fadd2(q1, q2));
                        }
                    }
                }
            }

            // batched reductions: 5 groups of 4 pairs, 6 shfl each.
            // octet (lane>>3) gets pair j = 4*g + (lane>>3), replicated 8x.
#pragma unroll
            for (int g = 0; g < 5; ++g) {
                float z = bfly4(p[4*g], p[4*g+1], p[4*g+2], p[4*g+3], lane);
                int jme = 4 * g + (lane >> 3);
                int dme = pair_d(jme);
                float contrib = (tt + dme < rEnd) ? fmaxf(0.5f - z, 0.f) : 0.f;
                accD += contrib;
            }
        }

        // ── wait for copy C_i (issued last step), normalize its rows ─────
        if (i >= 1) {
            int cs = t0 + (RING - CHUNK) + CHUNK * i;   // t0 + 51 + 32i
            if (cs < rEnd) {
                mbar_wait(mbar, (u32)(i & 1));
                int ce = (cs + CHUNK < rEnd) ? (cs + CHUNK) : rEnd;
                for (int r = cs + wid; r < ce; r += NWARPS)
                    norm_row(rows, (r - t0) % RING, lane);
            }
        }
        __syncthreads();

        // ── issue copy C_{i+1}: overwrites this step's tile slots (safe) ─
        if (tid == 0) {
            int ns = t0 + (RING - CHUNK) + CHUNK * (i + 1);
            if (ns < rEnd) {
                int ne = (ns + CHUNK < rEnd) ? (ns + CHUNK) : rEnd;
                u32 bytes = (u32)(ne - ns) * ROWB;
                mbar_expect(mbar, bytes);
                int s0  = (ns - t0) % RING;
                int len = ne - ns;
                int l1  = (RING - s0 < len) ? (RING - s0) : len;
                bulk_g2s(sbase + (u32)s0 * ROWB, gbase + (size_t)ns * ROWB,
                         (u32)l1 * ROWB, mbar);
                if (l1 < len)
                    bulk_g2s(sbase, gbase + (size_t)(ns + l1) * ROWB,
                             (u32)(len - l1) * ROWB, mbar);
            }
        }
    }

    // ── block combine + grid ticket reduction ───────────────────────────
    float aWarp = wred(hsum2(accAa) + hsum2(accAb));
    float dWarp = wred(accD) * 0.125f;   // each pair counted by 8 lanes

    __shared__ float rA[NWARPS], rD[NWARPS];
    __shared__ int   sLast;
    if (lane == 0) { rA[wid] = aWarp; rD[wid] = dWarp; }
    __syncthreads();
    if (tid == 0) {
        float sA = 0.f, sD = 0.f;
#pragma unroll
        for (int w = 0; w < NWARPS; ++w) { sA += rA[w]; sD += rD[w]; }
        g_part[b * NSEG + seg] = make_float2(sA, sD);
        __threadfence();
        unsigned t = atomicAdd(&g_count, 1u);
        sLast = (t == NBLK - 1);
    }
    __syncthreads();

    if (sLast && tid < 32) {
        __threadfence();
        const float* gp = reinterpret_cast<const float*>(g_part);
        float a = 0.f, dd = 0.f;
        for (int i = tid; i < NBLK; i += 32) {
            a  += __ldcg(gp + 2 * i);
            dd += __ldcg(gp + 2 * i + 1);
        }
        a  = wred(a);
        dd = wred(dd);
        if (tid == 0) {
            float adj  = 1.f - a / ((float)NB * (float)(SS - 1));
            float dist = dd / ((float)NB * (float)CNT_DIST);
            out[0] = adj + dist;
            g_count = 0;                      // reset for next graph replay
        }
    }
}

extern "C" void kernel_launch(void* const* d_in, const int* in_sizes, int n_in,
                              void* d_out, int out_size) {
    (void)in_sizes; (void)n_in; (void)out_size;
    const float* hs = (const float*)d_in[0];

    const size_t shmem = (size_t)RING * ROWB + 16;   // rows + mbarrier
    cudaFuncSetAttribute(tcl_main, cudaFuncAttributeMaxDynamicSharedMemorySize,
                         (int)shmem);

    dim3 grid(NSEG, NB);
    tcl_main<<<grid, NTHR, shmem>>>(hs, (float*)d_out);
}